// round 12
// baseline (speedup 1.0000x reference)
#include <cuda_runtime.h>
#include <cuda_bf16.h>
#include <math.h>

#define HD 64
#define NE 1024
#define TT 4096
#define NB 4
#define BT (NB*TT)

typedef unsigned long long u64;
typedef unsigned int u32;

// ---- device scratch (no allocs allowed) ----
// W^T bf16 hi/lo, chunk-major + SW128-pre-swizzled: [chunk 16][n' 192][k 64]
__device__ __align__(128) __nv_bfloat16 g_wth[16*192*64];
__device__ __align__(128) __nv_bfloat16 g_wtl[16*192*64];
// q/k blocked: [tile 256][s 64][h 64] bf16, swizzled; v transposed: [tile][h 64][s 64]
__device__ __align__(128) __nv_bfloat16 g_qh[BT*HD];
__device__ __align__(128) __nv_bfloat16 g_ql[BT*HD];
__device__ __align__(128) __nv_bfloat16 g_kh[BT*HD];
__device__ __align__(128) __nv_bfloat16 g_vth[BT*HD];
__device__ __align__(128) __nv_bfloat16 g_vtl[BT*HD];

// ---------------- PTX helpers ----------------
__device__ __forceinline__ u32 s2u(const void* p) {
    return (u32)__cvta_generic_to_shared(p);
}
__device__ __forceinline__ void mbar_init(u32 mb, u32 cnt) {
    asm volatile("mbarrier.init.shared.b64 [%0], %1;" :: "r"(mb), "r"(cnt) : "memory");
}
__device__ __forceinline__ void mbar_expect(u32 mb, u32 tx) {
    asm volatile("mbarrier.arrive.expect_tx.shared.b64 _, [%0], %1;" :: "r"(mb), "r"(tx) : "memory");
}
__device__ __forceinline__ void bulk_g2s(u32 dst, const void* src, u32 bytes, u32 mb) {
    asm volatile("cp.async.bulk.shared::cluster.global.mbarrier::complete_tx::bytes [%0], [%1], %2, [%3];"
                 :: "r"(dst), "l"(src), "r"(bytes), "r"(mb) : "memory");
}
__device__ __forceinline__ void waitpar(u32 mb, u32 ph) {
    asm volatile(
        "{\n\t.reg .pred P;\n"
        "W%=:\n\t"
        "mbarrier.try_wait.parity.acquire.cta.shared::cta.b64 P, [%0], %1, 0x989680;\n\t"
        "@P bra D%=;\n\t"
        "bra W%=;\n"
        "D%=:\n\t}"
        :: "r"(mb), "r"(ph) : "memory");
}
// bf16x2 pack: low half = lo param, high half = hi param
__device__ __forceinline__ u32 bf2(float lo, float hi) {
    u32 d; asm("cvt.rn.bf16x2.f32 %0, %1, %2;" : "=r"(d) : "f"(hi), "f"(lo));
    return d;
}
__device__ __forceinline__ float lo16f(u32 h) { return __uint_as_float(h << 16); }
__device__ __forceinline__ float hi16f(u32 h) { return __uint_as_float(h & 0xFFFF0000u); }
__device__ __forceinline__ void ldsm4(u32* r, u32 addr) {
    asm volatile("ldmatrix.sync.aligned.m8n8.x4.shared.b16 {%0,%1,%2,%3}, [%4];"
        : "=r"(r[0]), "=r"(r[1]), "=r"(r[2]), "=r"(r[3]) : "r"(addr));
}
__device__ __forceinline__ void ldsm2(u32* r, u32 addr) {
    asm volatile("ldmatrix.sync.aligned.m8n8.x2.shared.b16 {%0,%1}, [%2];"
        : "=r"(r[0]), "=r"(r[1]) : "r"(addr));
}
__device__ __forceinline__ void mma_bf16(float* c, const u32* a, const u32* b) {
    asm volatile("mma.sync.aligned.m16n8k16.row.col.f32.bf16.bf16.f32 "
        "{%0,%1,%2,%3}, {%4,%5,%6,%7}, {%8,%9}, {%0,%1,%2,%3};"
        : "+f"(c[0]), "+f"(c[1]), "+f"(c[2]), "+f"(c[3])
        : "r"(a[0]), "r"(a[1]), "r"(a[2]), "r"(a[3]), "r"(b[0]), "r"(b[1]));
}
__device__ __forceinline__ u32 abyte(int row, int q) {
    return (u32)(row * 128 + (((q) ^ (row & 7)) << 4));
}

// ---------------------------------------------------------------------------
// Kernel 0: W transpose + bf16 hi/lo + chunk-major SW128 pre-swizzle. (R6)
// ---------------------------------------------------------------------------
__global__ void wconv_kernel(const float* __restrict__ Wk,
                             const float* __restrict__ Wq,
                             const float* __restrict__ Wv)
{
    int np  = blockIdx.x;            // 0..191
    int mat = np >> 6;
    int n   = np & 63;
    const float* W = (mat == 0) ? Wk : (mat == 1) ? Wq : Wv;
    char* dh = (char*)g_wth;
    char* dl = (char*)g_wtl;
    for (int k = threadIdx.x; k < NE; k += blockDim.x) {
        float v = W[k * HD + n];
        __nv_bfloat16 h = __float2bfloat16(v);
        float hf = __bfloat162float(h);
        __nv_bfloat16 l = __float2bfloat16(v - hf);
        int ch = k >> 6, kc = k & 63;
        u32 off = (u32)np * 128 + kc * 2;
        u32 sw  = off ^ ((np & 7) * 16);
        *(__nv_bfloat16*)(dh + ch * 24576 + sw) = h;
        *(__nv_bfloat16*)(dl + ch * 24576 + sw) = l;
    }
}

// ---------------------------------------------------------------------------
// Kernel 1: QKV projection via mma.sync bf16 hi/lo, N-split for co-residency.
// CTA: 128 rows x 96 cols (blockIdx.y selects col half). 256 thr, 8 warps
// (4M x 2N), warp 32x48. W half-tiles double-buffered via cp.async.bulk.
// smem 82048B -> 90112 after 8KB granularity -> TRUE 2 CTAs/SM; 256 CTAs
// = one full wave over 148 SMs.
// ---------------------------------------------------------------------------
#define NCH 16
#define OFF_XH 128
#define OFF_XL (128 + 16384)
#define OFF_W  (128 + 32768)
#define WSTRIDE 24576
#define P_SMEM (OFF_W + 2*WSTRIDE)      // 82048

__global__ __launch_bounds__(256, 2) void proj_kernel(const float* __restrict__ x)
{
    extern __shared__ char sm[];
    const u32 smb = s2u(sm);
    const int tid  = threadIdx.x;
    const int warp = tid >> 5;
    const int lane = tid & 31;
    const int wm   = warp >> 1;
    const int wn   = warp & 1;
    const int row0 = blockIdx.x * 128;
    const int nh   = blockIdx.y;            // 0..1 : 96-col half

    const u32 mb0 = smb;
    const u32 mb1 = smb + 8;

    if (tid == 0) { mbar_init(mb0, 1); mbar_init(mb1, 1); }
    __syncthreads();

    const char* wh_g = (const char*)g_wth + nh * 12288;
    const char* wl_g = (const char*)g_wtl + nh * 12288;

    if (tid == 0) {
        mbar_expect(mb0, 24576);
        bulk_g2s(smb + OFF_W,         wh_g, 12288, mb0);
        bulk_g2s(smb + OFF_W + 12288, wl_g, 12288, mb0);
        mbar_expect(mb1, 24576);
        bulk_g2s(smb + OFF_W + WSTRIDE,         wh_g + 24576, 12288, mb1);
        bulk_g2s(smb + OFF_W + WSTRIDE + 12288, wl_g + 24576, 12288, mb1);
    }

    float C[2][6][4];
    #pragma unroll
    for (int mt = 0; mt < 2; mt++)
        #pragma unroll
        for (int nt = 0; nt < 6; nt++)
            #pragma unroll
            for (int i = 0; i < 4; i++) C[mt][nt][i] = 0.f;

    float4 xr[8];
    #pragma unroll
    for (int i = 0; i < 8; i++) {
        int idx = tid + i * 256;
        int r = idx >> 4, c4 = idx & 15;
        xr[i] = *(const float4*)&x[(size_t)(row0 + r) * NE + c4 * 4];
    }
    #pragma unroll
    for (int i = 0; i < 8; i++) {
        int idx = tid + i * 256;
        int r = idx >> 4, c4 = idx & 15;
        float4 v = xr[i];
        u32 h01 = bf2(v.x, v.y);
        u32 h23 = bf2(v.z, v.w);
        u32 l01 = bf2(v.x - lo16f(h01), v.y - hi16f(h01));
        u32 l23 = bf2(v.z - lo16f(h23), v.w - hi16f(h23));
        u32 off = (u32)r * 128 + c4 * 8;
        u32 sw  = off ^ ((r & 7) * 16);
        *(u64*)(sm + OFF_XH + sw) = (u64)h01 | ((u64)h23 << 32);
        *(u64*)(sm + OFF_XL + sw) = (u64)l01 | ((u64)l23 << 32);
    }
    __syncthreads();

    u32 ph[2] = {0, 0};
    const int rowA0 = wm * 32 + (lane & 15);
    const int qselA = lane >> 4;
    const int nrow0 = wn * 48 + (lane & 7);
    const int gB    = (lane >> 3) & 1;

    for (int c = 0; c < NCH; c++) {
        if (c < NCH - 1) {
            const int kk = (c + 1) * 64;
            #pragma unroll
            for (int i = 0; i < 8; i++) {
                int idx = tid + i * 256;
                int r = idx >> 4, c4 = idx & 15;
                xr[i] = *(const float4*)&x[(size_t)(row0 + r) * NE + kk + c4 * 4];
            }
        }

        waitpar((c & 1) ? mb1 : mb0, ph[c & 1]);
        ph[c & 1] ^= 1;

        const u32 wbase = smb + OFF_W + (c & 1) * WSTRIDE;

        #pragma unroll
        for (int ks = 0; ks < 4; ks++) {
            u32 ah[2][4], al[2][4];
            #pragma unroll
            for (int mt = 0; mt < 2; mt++) {
                u32 ba = abyte(rowA0 + mt * 16, ks * 2 + qselA);
                ldsm4(ah[mt], smb + OFF_XH + ba);
                ldsm4(al[mt], smb + OFF_XL + ba);
            }
            #pragma unroll
            for (int nt = 0; nt < 6; nt++) {
                u32 bh[2], bl[2];
                u32 bb = abyte(nrow0 + nt * 8, ks * 2 + gB);
                ldsm2(bh, wbase + bb);
                ldsm2(bl, wbase + 12288 + bb);
                #pragma unroll
                for (int mt = 0; mt < 2; mt++) {
                    mma_bf16(C[mt][nt], ah[mt], bh);
                    mma_bf16(C[mt][nt], ah[mt], bl);
                    mma_bf16(C[mt][nt], al[mt], bh);
                }
            }
        }
        __syncthreads();

        if (c < NCH - 1) {
            #pragma unroll
            for (int i = 0; i < 8; i++) {
                int idx = tid + i * 256;
                int r = idx >> 4, c4 = idx & 15;
                float4 v = xr[i];
                u32 h01 = bf2(v.x, v.y);
                u32 h23 = bf2(v.z, v.w);
                u32 l01 = bf2(v.x - lo16f(h01), v.y - hi16f(h01));
                u32 l23 = bf2(v.z - lo16f(h23), v.w - hi16f(h23));
                u32 off = (u32)r * 128 + c4 * 8;
                u32 sw  = off ^ ((r & 7) * 16);
                *(u64*)(sm + OFF_XH + sw) = (u64)h01 | ((u64)h23 << 32);
                *(u64*)(sm + OFF_XL + sw) = (u64)l01 | ((u64)l23 << 32);
            }
            if (tid == 0 && c + 2 < NCH) {
                u32 mb = (c & 1) ? mb1 : mb0;
                u32 dst = smb + OFF_W + (c & 1) * WSTRIDE;
                mbar_expect(mb, 24576);
                bulk_g2s(dst,         wh_g + (size_t)(c + 2) * 24576, 12288, mb);
                bulk_g2s(dst + 12288, wl_g + (size_t)(c + 2) * 24576, 12288, mb);
            }
        }
        __syncthreads();
    }

    // ---- epilogue: q/k blocked [tile][s][h], v^T [tile][h][s], hi/lo bf16 ----
    #pragma unroll
    for (int mt = 0; mt < 2; mt++) {
        int r_lo = row0 + wm * 32 + mt * 16 + (lane >> 2);
        size_t tb = (size_t)(r_lo >> 6) * 8192;
        int s0 = r_lo & 63, s1 = s0 + 8;
        #pragma unroll
        for (int nt = 0; nt < 6; nt++) {
            int col = nh * 96 + wn * 48 + nt * 8 + 2 * (lane & 3);
            int mat = col >> 6;
            int h   = col & 63;
            float sc = (mat == 1) ? 0.03125f : 1.0f;   // 1024^-0.5 folded into q
            float v0 = C[mt][nt][0] * sc, v1 = C[mt][nt][1] * sc;
            float v2 = C[mt][nt][2] * sc, v3 = C[mt][nt][3] * sc;
            if (mat != 2) {
                char* dh = (mat == 0) ? (char*)g_kh : (char*)g_qh;
                u32 h01 = bf2(v0, v1);
                u32 h23 = bf2(v2, v3);
                size_t a0 = tb + s0 * 128 + ((((h >> 3) ^ (s0 & 7)) << 4) + (h & 7) * 2);
                size_t a1 = tb + s1 * 128 + ((((h >> 3) ^ (s1 & 7)) << 4) + (h & 7) * 2);
                *(u32*)(dh + a0) = h01;
                *(u32*)(dh + a1) = h23;
                if (mat == 1) {   // q also needs lo part (used in S = QhKh + QlKh)
                    u32 l01 = bf2(v0 - lo16f(h01), v1 - hi16f(h01));
                    u32 l23 = bf2(v2 - lo16f(h23), v3 - hi16f(h23));
                    *(u32*)((char*)g_ql + a0) = l01;
                    *(u32*)((char*)g_ql + a1) = l23;
                }
            } else {
                char* dh = (char*)g_vth;
                char* dl = (char*)g_vtl;
                float vv[4] = {v0, v1, v2, v3};
                #pragma unroll
                for (int e = 0; e < 4; e++) {
                    int hh = h + (e & 1);
                    int ss = (e < 2) ? s0 : s1;
                    __nv_bfloat16 bh = __float2bfloat16(vv[e]);
                    __nv_bfloat16 bl = __float2bfloat16(vv[e] - __bfloat162float(bh));
                    size_t a = tb + hh * 128 + ((((ss >> 3) ^ (hh & 7)) << 4) + (ss & 7) * 2);
                    *(__nv_bfloat16*)(dh + a) = bh;
                    *(__nv_bfloat16*)(dl + a) = bl;
                }
            }
        }
    }
}

// ---------------------------------------------------------------------------
// Kernel 2: causal flash attention via mma.sync:
//   S  = QhKh + QlKh          (K-lo never stored/loaded — err ~3e-4, safe)
//   PV = PhVh + PhVl + PlVh   (full hi/lo — the PV lo-drop was the R10 failure)
// CTA = 128 threads (4 warps), q-tile M=64, BK=64 stages double-buffered.
// CTA processes tile pair (tq, 63-tq): uniform 65 stages. (R6 structure)
// ---------------------------------------------------------------------------
#define A_QH  128
#define A_QL  (128 + 8192)
#define A_ST  (128 + 16384)
#define A_STG 24576
#define A_SMEM (A_ST + 2*A_STG)      // 65664

__global__ __launch_bounds__(128) void attn2_kernel(float* __restrict__ out)
{
    extern __shared__ char sm[];
    const u32 smb = s2u(sm);
    const int tid  = threadIdx.x;
    const int warp = tid >> 5;
    const int lane = tid & 31;
    const int b    = blockIdx.y;
    const int pidx = blockIdx.x;      // 0..31

    const u32 mb0 = smb, mb1 = smb + 8;
    if (tid == 0) { mbar_init(mb0, 1); mbar_init(mb1, 1); }
    __syncthreads();

    u32 ph[2] = {0, 0};

    // ldmatrix geometry
    const int lrowA = warp * 16 + (lane & 15);
    const int lqA   = lane >> 4;
    const int browB = ((lane >> 4) << 3) + (lane & 7);
    const int bgB   = (lane >> 3) & 1;

    const char* qh_g  = (const char*)g_qh;
    const char* ql_g  = (const char*)g_ql;
    const char* kh_g  = (const char*)g_kh;
    const char* vth_g = (const char*)g_vth;
    const char* vtl_g = (const char*)g_vtl;

    for (int ti = 0; ti < 2; ti++) {
        const int tq     = ti ? (63 - pidx) : pidx;
        const int n_iter = tq + 1;
        const size_t tgq = (size_t)(b * 64 + tq) * 8192;

        __syncthreads();   // previous tile's buffer consumers done
        if (tid == 0) {
            const size_t t0 = (size_t)(b * 64) * 8192;
            mbar_expect(mb0, 16384 + A_STG);
            bulk_g2s(smb + A_QH, qh_g + tgq, 8192, mb0);
            bulk_g2s(smb + A_QL, ql_g + tgq, 8192, mb0);
            u32 d = smb + A_ST;
            bulk_g2s(d,         kh_g  + t0, 8192, mb0);
            bulk_g2s(d + 8192,  vth_g + t0, 8192, mb0);
            bulk_g2s(d + 16384, vtl_g + t0, 8192, mb0);
            if (n_iter > 1) {
                const size_t t1 = t0 + 8192;
                u32 d1 = d + A_STG;
                mbar_expect(mb1, A_STG);
                bulk_g2s(d1,         kh_g  + t1, 8192, mb1);
                bulk_g2s(d1 + 8192,  vth_g + t1, 8192, mb1);
                bulk_g2s(d1 + 16384, vtl_g + t1, 8192, mb1);
            }
        }
        waitpar(mb0, ph[0]); ph[0] ^= 1;

        // Q frags (persistent in registers)
        u32 qfh[4][4], qfl[4][4];
        #pragma unroll
        for (int ks = 0; ks < 4; ks++) {
            u32 off = abyte(lrowA, ks * 2 + lqA);
            ldsm4(qfh[ks], smb + A_QH + off);
            ldsm4(qfl[ks], smb + A_QL + off);
        }

        float o[8][4];
        #pragma unroll
        for (int nt = 0; nt < 8; nt++)
            #pragma unroll
            for (int i = 0; i < 4; i++) o[nt][i] = 0.f;
        float m0 = -1e30f, m1 = -1e30f, l0 = 0.f, l1 = 0.f;

        for (int gi = 0; gi < n_iter; gi++) {
            const int s = gi & 1;
            if (gi > 0) { waitpar(s ? mb1 : mb0, ph[s]); ph[s] ^= 1; }
            const u32 kb = smb + A_ST + s * A_STG;
            const u32 vbh = kb + 8192;
            const u32 vbl = kb + 16384;

            // ---- S = Qh K^T + Ql K^T ----
            float sacc[8][4];
            #pragma unroll
            for (int nt = 0; nt < 8; nt++)
                #pragma unroll
                for (int i = 0; i < 4; i++) sacc[nt][i] = 0.f;

            #pragma unroll
            for (int ks = 0; ks < 4; ks++) {
                #pragma unroll
                for (int ntp = 0; ntp < 4; ntp++) {
                    int nr = ntp * 16 + browB;
                    u32 off = (u32)(nr * 128 + (((ks * 2 + bgB) ^ (nr & 7)) << 4));
                    u32 kh4[4];
                    ldsm4(kh4, kb + off);
                    mma_bf16(sacc[2*ntp],   qfh[ks], kh4);
                    mma_bf16(sacc[2*ntp],   qfl[ks], kh4);
                    mma_bf16(sacc[2*ntp+1], qfh[ks], kh4 + 2);
                    mma_bf16(sacc[2*ntp+1], qfl[ks], kh4 + 2);
                }
            }

            // ---- causal mask (diagonal stage only) ----
            if (gi == tq) {
                int rl = warp * 16 + (lane >> 2);
                #pragma unroll
                for (int nt = 0; nt < 8; nt++) {
                    int cl = nt * 8 + 2 * (lane & 3);
                    if (cl     > rl)     sacc[nt][0] = -1e30f;
                    if (cl + 1 > rl)     sacc[nt][1] = -1e30f;
                    if (cl     > rl + 8) sacc[nt][2] = -1e30f;
                    if (cl + 1 > rl + 8) sacc[nt][3] = -1e30f;
                }
            }

            // ---- online softmax ----
            float mx0 = sacc[0][0], mx1 = sacc[0][2];
            #pragma unroll
            for (int nt = 0; nt < 8; nt++) {
                mx0 = fmaxf(mx0, fmaxf(sacc[nt][0], sacc[nt][1]));
                mx1 = fmaxf(mx1, fmaxf(sacc[nt][2], sacc[nt][3]));
            }
            mx0 = fmaxf(mx0, __shfl_xor_sync(0xffffffffu, mx0, 1));
            mx0 = fmaxf(mx0, __shfl_xor_sync(0xffffffffu, mx0, 2));
            mx1 = fmaxf(mx1, __shfl_xor_sync(0xffffffffu, mx1, 1));
            mx1 = fmaxf(mx1, __shfl_xor_sync(0xffffffffu, mx1, 2));
            float mn0 = fmaxf(m0, mx0), mn1 = fmaxf(m1, mx1);
            float sc0 = __expf(m0 - mn0), sc1 = __expf(m1 - mn1);
            float sum0 = 0.f, sum1 = 0.f;
            #pragma unroll
            for (int nt = 0; nt < 8; nt++) {
                sacc[nt][0] = __expf(sacc[nt][0] - mn0);
                sacc[nt][1] = __expf(sacc[nt][1] - mn0);
                sacc[nt][2] = __expf(sacc[nt][2] - mn1);
                sacc[nt][3] = __expf(sacc[nt][3] - mn1);
                sum0 += sacc[nt][0] + sacc[nt][1];
                sum1 += sacc[nt][2] + sacc[nt][3];
            }
            sum0 += __shfl_xor_sync(0xffffffffu, sum0, 1);
            sum0 += __shfl_xor_sync(0xffffffffu, sum0, 2);
            sum1 += __shfl_xor_sync(0xffffffffu, sum1, 1);
            sum1 += __shfl_xor_sync(0xffffffffu, sum1, 2);
            l0 = l0 * sc0 + sum0;  l1 = l1 * sc1 + sum1;
            m0 = mn0;  m1 = mn1;
            #pragma unroll
            for (int nt = 0; nt < 8; nt++) {
                o[nt][0] *= sc0;  o[nt][1] *= sc0;
                o[nt][2] *= sc1;  o[nt][3] *= sc1;
            }

            // ---- O += PhVh + PhVl + PlVh (full hi/lo PV) ----
            #pragma unroll
            for (int kt = 0; kt < 4; kt++) {
                const float* sA = sacc[2*kt];
                const float* sB = sacc[2*kt+1];
                u32 pH[4], pL[4];
                pH[0] = bf2(sA[0], sA[1]);
                pH[1] = bf2(sA[2], sA[3]);
                pH[2] = bf2(sB[0], sB[1]);
                pH[3] = bf2(sB[2], sB[3]);
                pL[0] = bf2(sA[0] - lo16f(pH[0]), sA[1] - hi16f(pH[0]));
                pL[1] = bf2(sA[2] - lo16f(pH[1]), sA[3] - hi16f(pH[1]));
                pL[2] = bf2(sB[0] - lo16f(pH[2]), sB[1] - hi16f(pH[2]));
                pL[3] = bf2(sB[2] - lo16f(pH[3]), sB[3] - hi16f(pH[3]));
                #pragma unroll
                for (int ntp = 0; ntp < 4; ntp++) {
                    int nr = ntp * 16 + browB;
                    u32 off = (u32)(nr * 128 + (((kt * 2 + bgB) ^ (nr & 7)) << 4));
                    u32 vh4[4], vl4[4];
                    ldsm4(vh4, vbh + off);
                    ldsm4(vl4, vbl + off);
                    mma_bf16(o[2*ntp],   pH, vh4);
                    mma_bf16(o[2*ntp],   pH, vl4);
                    mma_bf16(o[2*ntp],   pL, vh4);
                    mma_bf16(o[2*ntp+1], pH, vh4 + 2);
                    mma_bf16(o[2*ntp+1], pH, vl4 + 2);
                    mma_bf16(o[2*ntp+1], pL, vh4 + 2);
                }
            }

            __syncthreads();
            if (tid == 0 && gi + 2 < n_iter) {
                const size_t tn = (size_t)(b * 64 + gi + 2) * 8192;
                u32 mb = s ? mb1 : mb0;
                u32 d  = smb + A_ST + s * A_STG;
                mbar_expect(mb, A_STG);
                bulk_g2s(d,         kh_g  + tn, 8192, mb);
                bulk_g2s(d + 8192,  vth_g + tn, 8192, mb);
                bulk_g2s(d + 16384, vtl_g + tn, 8192, mb);
            }
        }

        // ---- epilogue ----
        float i0 = 1.0f / l0, i1 = 1.0f / l1;
        int gr = b * TT + tq * 64 + warp * 16 + (lane >> 2);
        #pragma unroll
        for (int nt = 0; nt < 8; nt++) {
            int h = nt * 8 + 2 * (lane & 3);
            float2 w0 = make_float2(o[nt][0] * i0, o[nt][1] * i0);
            float2 w1 = make_float2(o[nt][2] * i1, o[nt][3] * i1);
            *(float2*)&out[(size_t)gr * HD + h]       = w0;
            *(float2*)&out[(size_t)(gr + 8) * HD + h] = w1;
        }
    }
}

extern "C" void kernel_launch(void* const* d_in, const int* in_sizes, int n_in,
                              void* d_out, int out_size)
{
    const float* x  = (const float*)d_in[0];
    const float* Wk = (const float*)d_in[1];
    const float* Wq = (const float*)d_in[2];
    const float* Wv = (const float*)d_in[3];
    float* out = (float*)d_out;

    cudaFuncSetAttribute(proj_kernel, cudaFuncAttributeMaxDynamicSharedMemorySize, P_SMEM);
    cudaFuncSetAttribute(attn2_kernel, cudaFuncAttributeMaxDynamicSharedMemorySize, A_SMEM);

    wconv_kernel<<<192, 256>>>(Wk, Wq, Wv);
    proj_kernel<<<dim3(BT / 128, 2), 256, P_SMEM>>>(x);
    attn2_kernel<<<dim3(32, NB), 128, A_SMEM>>>(out);
}

// round 13
// speedup vs baseline: 1.0363x; 1.0363x over previous
#include <cuda_runtime.h>
#include <cuda_bf16.h>
#include <math.h>

#define HD 64
#define NE 1024
#define TT 4096
#define NB 4
#define BT (NB*TT)

typedef unsigned long long u64;
typedef unsigned int u32;

// ---- device scratch (no allocs allowed) ----
// W^T bf16 hi/lo, chunk-major + SW128-pre-swizzled: [chunk 16][n' 192][k 64]
__device__ __align__(128) __nv_bfloat16 g_wth[16*192*64];
__device__ __align__(128) __nv_bfloat16 g_wtl[16*192*64];
// q/k blocked: [tile 256][s 64][h 64] bf16, swizzled; v transposed: [tile][h 64][s 64]
__device__ __align__(128) __nv_bfloat16 g_qh[BT*HD];
__device__ __align__(128) __nv_bfloat16 g_ql[BT*HD];
__device__ __align__(128) __nv_bfloat16 g_kh[BT*HD];
__device__ __align__(128) __nv_bfloat16 g_vth[BT*HD];
__device__ __align__(128) __nv_bfloat16 g_vtl[BT*HD];

// ---------------- PTX helpers ----------------
__device__ __forceinline__ u32 s2u(const void* p) {
    return (u32)__cvta_generic_to_shared(p);
}
__device__ __forceinline__ void mbar_init(u32 mb, u32 cnt) {
    asm volatile("mbarrier.init.shared.b64 [%0], %1;" :: "r"(mb), "r"(cnt) : "memory");
}
__device__ __forceinline__ void mbar_expect(u32 mb, u32 tx) {
    asm volatile("mbarrier.arrive.expect_tx.shared.b64 _, [%0], %1;" :: "r"(mb), "r"(tx) : "memory");
}
__device__ __forceinline__ void bulk_g2s(u32 dst, const void* src, u32 bytes, u32 mb) {
    asm volatile("cp.async.bulk.shared::cluster.global.mbarrier::complete_tx::bytes [%0], [%1], %2, [%3];"
                 :: "r"(dst), "l"(src), "r"(bytes), "r"(mb) : "memory");
}
__device__ __forceinline__ void waitpar(u32 mb, u32 ph) {
    asm volatile(
        "{\n\t.reg .pred P;\n"
        "W%=:\n\t"
        "mbarrier.try_wait.parity.acquire.cta.shared::cta.b64 P, [%0], %1, 0x989680;\n\t"
        "@P bra D%=;\n\t"
        "bra W%=;\n"
        "D%=:\n\t}"
        :: "r"(mb), "r"(ph) : "memory");
}
// bf16x2 pack: low half = lo param, high half = hi param
__device__ __forceinline__ u32 bf2(float lo, float hi) {
    u32 d; asm("cvt.rn.bf16x2.f32 %0, %1, %2;" : "=r"(d) : "f"(hi), "f"(lo));
    return d;
}
__device__ __forceinline__ float lo16f(u32 h) { return __uint_as_float(h << 16); }
__device__ __forceinline__ float hi16f(u32 h) { return __uint_as_float(h & 0xFFFF0000u); }
__device__ __forceinline__ void ldsm4(u32* r, u32 addr) {
    asm volatile("ldmatrix.sync.aligned.m8n8.x4.shared.b16 {%0,%1,%2,%3}, [%4];"
        : "=r"(r[0]), "=r"(r[1]), "=r"(r[2]), "=r"(r[3]) : "r"(addr));
}
__device__ __forceinline__ void ldsm2(u32* r, u32 addr) {
    asm volatile("ldmatrix.sync.aligned.m8n8.x2.shared.b16 {%0,%1}, [%2];"
        : "=r"(r[0]), "=r"(r[1]) : "r"(addr));
}
__device__ __forceinline__ void mma_bf16(float* c, const u32* a, const u32* b) {
    asm volatile("mma.sync.aligned.m16n8k16.row.col.f32.bf16.bf16.f32 "
        "{%0,%1,%2,%3}, {%4,%5,%6,%7}, {%8,%9}, {%0,%1,%2,%3};"
        : "+f"(c[0]), "+f"(c[1]), "+f"(c[2]), "+f"(c[3])
        : "r"(a[0]), "r"(a[1]), "r"(a[2]), "r"(a[3]), "r"(b[0]), "r"(b[1]));
}
__device__ __forceinline__ u32 abyte(int row, int q) {
    return (u32)(row * 128 + (((q) ^ (row & 7)) << 4));
}

// ---------------------------------------------------------------------------
// Kernel 0: W transpose + bf16 hi/lo + chunk-major SW128 pre-swizzle. (R6)
// ---------------------------------------------------------------------------
__global__ void wconv_kernel(const float* __restrict__ Wk,
                             const float* __restrict__ Wq,
                             const float* __restrict__ Wv)
{
    int np  = blockIdx.x;            // 0..191
    int mat = np >> 6;
    int n   = np & 63;
    const float* W = (mat == 0) ? Wk : (mat == 1) ? Wq : Wv;
    char* dh = (char*)g_wth;
    char* dl = (char*)g_wtl;
    for (int k = threadIdx.x; k < NE; k += blockDim.x) {
        float v = W[k * HD + n];
        __nv_bfloat16 h = __float2bfloat16(v);
        float hf = __bfloat162float(h);
        __nv_bfloat16 l = __float2bfloat16(v - hf);
        int ch = k >> 6, kc = k & 63;
        u32 off = (u32)np * 128 + kc * 2;
        u32 sw  = off ^ ((np & 7) * 16);
        *(__nv_bfloat16*)(dh + ch * 24576 + sw) = h;
        *(__nv_bfloat16*)(dl + ch * 24576 + sw) = l;
    }
}

// ---------------------------------------------------------------------------
// Kernel 1: QKV projection via mma.sync bf16 hi/lo (exact R6 structure: 128
// rows x 192 cols, 256 thr, 8 warps (4M x 2N), warp 32x96; W double-buffered
// via cp.async.bulk; x staged ONCE per chunk). Epilogue: k hi only, q hi+lo,
// v^T hi/lo.
// ---------------------------------------------------------------------------
#define NCH 16
#define OFF_XH 128
#define OFF_XL (128 + 16384)
#define OFF_W  (128 + 32768)
#define WSTRIDE 49152
#define P_SMEM (OFF_W + 2*WSTRIDE)

__global__ __launch_bounds__(256, 1) void proj_kernel(const float* __restrict__ x)
{
    extern __shared__ char sm[];
    const u32 smb = s2u(sm);
    const int tid  = threadIdx.x;
    const int warp = tid >> 5;
    const int lane = tid & 31;
    const int wm   = warp >> 1;
    const int wn   = warp & 1;
    const int row0 = blockIdx.x * 128;

    const u32 mb0 = smb;
    const u32 mb1 = smb + 8;

    if (tid == 0) { mbar_init(mb0, 1); mbar_init(mb1, 1); }
    __syncthreads();

    const char* wh_g = (const char*)g_wth;
    const char* wl_g = (const char*)g_wtl;

    if (tid == 0) {
        mbar_expect(mb0, 49152);
        bulk_g2s(smb + OFF_W,         wh_g, 24576, mb0);
        bulk_g2s(smb + OFF_W + 24576, wl_g, 24576, mb0);
        mbar_expect(mb1, 49152);
        bulk_g2s(smb + OFF_W + WSTRIDE,         wh_g + 24576, 24576, mb1);
        bulk_g2s(smb + OFF_W + WSTRIDE + 24576, wl_g + 24576, 24576, mb1);
    }

    float C[2][12][4];
    #pragma unroll
    for (int mt = 0; mt < 2; mt++)
        #pragma unroll
        for (int nt = 0; nt < 12; nt++)
            #pragma unroll
            for (int i = 0; i < 4; i++) C[mt][nt][i] = 0.f;

    float4 xr[8];
    #pragma unroll
    for (int i = 0; i < 8; i++) {
        int idx = tid + i * 256;
        int r = idx >> 4, c4 = idx & 15;
        xr[i] = *(const float4*)&x[(size_t)(row0 + r) * NE + c4 * 4];
    }
    #pragma unroll
    for (int i = 0; i < 8; i++) {
        int idx = tid + i * 256;
        int r = idx >> 4, c4 = idx & 15;
        float4 v = xr[i];
        u32 h01 = bf2(v.x, v.y);
        u32 h23 = bf2(v.z, v.w);
        u32 l01 = bf2(v.x - lo16f(h01), v.y - hi16f(h01));
        u32 l23 = bf2(v.z - lo16f(h23), v.w - hi16f(h23));
        u32 off = (u32)r * 128 + c4 * 8;
        u32 sw  = off ^ ((r & 7) * 16);
        *(u64*)(sm + OFF_XH + sw) = (u64)h01 | ((u64)h23 << 32);
        *(u64*)(sm + OFF_XL + sw) = (u64)l01 | ((u64)l23 << 32);
    }
    __syncthreads();

    u32 ph[2] = {0, 0};
    const int rowA0 = wm * 32 + (lane & 15);
    const int qselA = lane >> 4;
    const int nrow0 = wn * 96 + (lane & 7);
    const int gB    = (lane >> 3) & 1;

    for (int c = 0; c < NCH; c++) {
        if (c < NCH - 1) {
            const int kk = (c + 1) * 64;
            #pragma unroll
            for (int i = 0; i < 8; i++) {
                int idx = tid + i * 256;
                int r = idx >> 4, c4 = idx & 15;
                xr[i] = *(const float4*)&x[(size_t)(row0 + r) * NE + kk + c4 * 4];
            }
        }

        waitpar((c & 1) ? mb1 : mb0, ph[c & 1]);
        ph[c & 1] ^= 1;

        const u32 wbase = smb + OFF_W + (c & 1) * WSTRIDE;

        #pragma unroll
        for (int ks = 0; ks < 4; ks++) {
            u32 ah[2][4], al[2][4];
            #pragma unroll
            for (int mt = 0; mt < 2; mt++) {
                u32 ba = abyte(rowA0 + mt * 16, ks * 2 + qselA);
                ldsm4(ah[mt], smb + OFF_XH + ba);
                ldsm4(al[mt], smb + OFF_XL + ba);
            }
            #pragma unroll
            for (int nt = 0; nt < 12; nt++) {
                u32 bh[2], bl[2];
                u32 bb = abyte(nrow0 + nt * 8, ks * 2 + gB);
                ldsm2(bh, wbase + bb);
                ldsm2(bl, wbase + 24576 + bb);
                #pragma unroll
                for (int mt = 0; mt < 2; mt++) {
                    mma_bf16(C[mt][nt], ah[mt], bh);
                    mma_bf16(C[mt][nt], ah[mt], bl);
                    mma_bf16(C[mt][nt], al[mt], bh);
                }
            }
        }
        __syncthreads();

        if (c < NCH - 1) {
            #pragma unroll
            for (int i = 0; i < 8; i++) {
                int idx = tid + i * 256;
                int r = idx >> 4, c4 = idx & 15;
                float4 v = xr[i];
                u32 h01 = bf2(v.x, v.y);
                u32 h23 = bf2(v.z, v.w);
                u32 l01 = bf2(v.x - lo16f(h01), v.y - hi16f(h01));
                u32 l23 = bf2(v.z - lo16f(h23), v.w - hi16f(h23));
                u32 off = (u32)r * 128 + c4 * 8;
                u32 sw  = off ^ ((r & 7) * 16);
                *(u64*)(sm + OFF_XH + sw) = (u64)h01 | ((u64)h23 << 32);
                *(u64*)(sm + OFF_XL + sw) = (u64)l01 | ((u64)l23 << 32);
            }
            if (tid == 0 && c + 2 < NCH) {
                u32 mb = (c & 1) ? mb1 : mb0;
                u32 dst = smb + OFF_W + (c & 1) * WSTRIDE;
                mbar_expect(mb, 49152);
                bulk_g2s(dst,         wh_g + (size_t)(c + 2) * 24576, 24576, mb);
                bulk_g2s(dst + 24576, wl_g + (size_t)(c + 2) * 24576, 24576, mb);
            }
        }
        __syncthreads();
    }

    // ---- epilogue: k hi, q hi+lo (blocked [tile][s][h]), v^T hi/lo ----
    #pragma unroll
    for (int mt = 0; mt < 2; mt++) {
        int r_lo = row0 + wm * 32 + mt * 16 + (lane >> 2);
        size_t tb = (size_t)(r_lo >> 6) * 8192;
        int s0 = r_lo & 63, s1 = s0 + 8;
        #pragma unroll
        for (int nt = 0; nt < 12; nt++) {
            int col = wn * 96 + nt * 8 + 2 * (lane & 3);
            int mat = col >> 6;
            int h   = col & 63;
            float sc = (mat == 1) ? 0.03125f : 1.0f;   // 1024^-0.5 folded into q
            float v0 = C[mt][nt][0] * sc, v1 = C[mt][nt][1] * sc;
            float v2 = C[mt][nt][2] * sc, v3 = C[mt][nt][3] * sc;
            if (mat != 2) {
                char* dh = (mat == 0) ? (char*)g_kh : (char*)g_qh;
                u32 h01 = bf2(v0, v1);
                u32 h23 = bf2(v2, v3);
                size_t a0 = tb + s0 * 128 + ((((h >> 3) ^ (s0 & 7)) << 4) + (h & 7) * 2);
                size_t a1 = tb + s1 * 128 + ((((h >> 3) ^ (s1 & 7)) << 4) + (h & 7) * 2);
                *(u32*)(dh + a0) = h01;
                *(u32*)(dh + a1) = h23;
                if (mat == 1) {   // q lo needed: S = QhKh + QlKh
                    u32 l01 = bf2(v0 - lo16f(h01), v1 - hi16f(h01));
                    u32 l23 = bf2(v2 - lo16f(h23), v3 - hi16f(h23));
                    *(u32*)((char*)g_ql + a0) = l01;
                    *(u32*)((char*)g_ql + a1) = l23;
                }
            } else {
                char* dh = (char*)g_vth;
                char* dl = (char*)g_vtl;
                float vv[4] = {v0, v1, v2, v3};
                #pragma unroll
                for (int e = 0; e < 4; e++) {
                    int hh = h + (e & 1);
                    int ss = (e < 2) ? s0 : s1;
                    __nv_bfloat16 bh = __float2bfloat16(vv[e]);
                    __nv_bfloat16 bl = __float2bfloat16(vv[e] - __bfloat162float(bh));
                    size_t a = tb + hh * 128 + ((((ss >> 3) ^ (hh & 7)) << 4) + (ss & 7) * 2);
                    *(__nv_bfloat16*)(dh + a) = bh;
                    *(__nv_bfloat16*)(dl + a) = bl;
                }
            }
        }
    }
}

// ---------------------------------------------------------------------------
// Kernel 2: causal flash attention via mma.sync (exact R11 version):
//   S  = QhKh + QlKh          (K-lo never stored/loaded — err ~3e-4, verified)
//   PV = PhVh + PhVl + PlVh   (full hi/lo)
// CTA = 128 threads (4 warps), q-tile M=64, BK=64 stages double-buffered.
// CTA processes tile pair (tq, 63-tq): uniform 65 stages.
// ---------------------------------------------------------------------------
#define A_QH  128
#define A_QL  (128 + 8192)
#define A_ST  (128 + 16384)
#define A_STG 24576
#define A_SMEM (A_ST + 2*A_STG)      // 65664

__global__ __launch_bounds__(128) void attn2_kernel(float* __restrict__ out)
{
    extern __shared__ char sm[];
    const u32 smb = s2u(sm);
    const int tid  = threadIdx.x;
    const int warp = tid >> 5;
    const int lane = tid & 31;
    const int b    = blockIdx.y;
    const int pidx = blockIdx.x;      // 0..31

    const u32 mb0 = smb, mb1 = smb + 8;
    if (tid == 0) { mbar_init(mb0, 1); mbar_init(mb1, 1); }
    __syncthreads();

    u32 ph[2] = {0, 0};

    // ldmatrix geometry
    const int lrowA = warp * 16 + (lane & 15);
    const int lqA   = lane >> 4;
    const int browB = ((lane >> 4) << 3) + (lane & 7);
    const int bgB   = (lane >> 3) & 1;

    const char* qh_g  = (const char*)g_qh;
    const char* ql_g  = (const char*)g_ql;
    const char* kh_g  = (const char*)g_kh;
    const char* vth_g = (const char*)g_vth;
    const char* vtl_g = (const char*)g_vtl;

    for (int ti = 0; ti < 2; ti++) {
        const int tq     = ti ? (63 - pidx) : pidx;
        const int n_iter = tq + 1;
        const size_t tgq = (size_t)(b * 64 + tq) * 8192;

        __syncthreads();   // previous tile's buffer consumers done
        if (tid == 0) {
            const size_t t0 = (size_t)(b * 64) * 8192;
            mbar_expect(mb0, 16384 + A_STG);
            bulk_g2s(smb + A_QH, qh_g + tgq, 8192, mb0);
            bulk_g2s(smb + A_QL, ql_g + tgq, 8192, mb0);
            u32 d = smb + A_ST;
            bulk_g2s(d,         kh_g  + t0, 8192, mb0);
            bulk_g2s(d + 8192,  vth_g + t0, 8192, mb0);
            bulk_g2s(d + 16384, vtl_g + t0, 8192, mb0);
            if (n_iter > 1) {
                const size_t t1 = t0 + 8192;
                u32 d1 = d + A_STG;
                mbar_expect(mb1, A_STG);
                bulk_g2s(d1,         kh_g  + t1, 8192, mb1);
                bulk_g2s(d1 + 8192,  vth_g + t1, 8192, mb1);
                bulk_g2s(d1 + 16384, vtl_g + t1, 8192, mb1);
            }
        }
        waitpar(mb0, ph[0]); ph[0] ^= 1;

        // Q frags (persistent in registers)
        u32 qfh[4][4], qfl[4][4];
        #pragma unroll
        for (int ks = 0; ks < 4; ks++) {
            u32 off = abyte(lrowA, ks * 2 + lqA);
            ldsm4(qfh[ks], smb + A_QH + off);
            ldsm4(qfl[ks], smb + A_QL + off);
        }

        float o[8][4];
        #pragma unroll
        for (int nt = 0; nt < 8; nt++)
            #pragma unroll
            for (int i = 0; i < 4; i++) o[nt][i] = 0.f;
        float m0 = -1e30f, m1 = -1e30f, l0 = 0.f, l1 = 0.f;

        for (int gi = 0; gi < n_iter; gi++) {
            const int s = gi & 1;
            if (gi > 0) { waitpar(s ? mb1 : mb0, ph[s]); ph[s] ^= 1; }
            const u32 kb = smb + A_ST + s * A_STG;
            const u32 vbh = kb + 8192;
            const u32 vbl = kb + 16384;

            // ---- S = Qh K^T + Ql K^T ----
            float sacc[8][4];
            #pragma unroll
            for (int nt = 0; nt < 8; nt++)
                #pragma unroll
                for (int i = 0; i < 4; i++) sacc[nt][i] = 0.f;

            #pragma unroll
            for (int ks = 0; ks < 4; ks++) {
                #pragma unroll
                for (int ntp = 0; ntp < 4; ntp++) {
                    int nr = ntp * 16 + browB;
                    u32 off = (u32)(nr * 128 + (((ks * 2 + bgB) ^ (nr & 7)) << 4));
                    u32 kh4[4];
                    ldsm4(kh4, kb + off);
                    mma_bf16(sacc[2*ntp],   qfh[ks], kh4);
                    mma_bf16(sacc[2*ntp],   qfl[ks], kh4);
                    mma_bf16(sacc[2*ntp+1], qfh[ks], kh4 + 2);
                    mma_bf16(sacc[2*ntp+1], qfl[ks], kh4 + 2);
                }
            }

            // ---- causal mask (diagonal stage only) ----
            if (gi == tq) {
                int rl = warp * 16 + (lane >> 2);
                #pragma unroll
                for (int nt = 0; nt < 8; nt++) {
                    int cl = nt * 8 + 2 * (lane & 3);
                    if (cl     > rl)     sacc[nt][0] = -1e30f;
                    if (cl + 1 > rl)     sacc[nt][1] = -1e30f;
                    if (cl     > rl + 8) sacc[nt][2] = -1e30f;
                    if (cl + 1 > rl + 8) sacc[nt][3] = -1e30f;
                }
            }

            // ---- online softmax ----
            float mx0 = sacc[0][0], mx1 = sacc[0][2];
            #pragma unroll
            for (int nt = 0; nt < 8; nt++) {
                mx0 = fmaxf(mx0, fmaxf(sacc[nt][0], sacc[nt][1]));
                mx1 = fmaxf(mx1, fmaxf(sacc[nt][2], sacc[nt][3]));
            }
            mx0 = fmaxf(mx0, __shfl_xor_sync(0xffffffffu, mx0, 1));
            mx0 = fmaxf(mx0, __shfl_xor_sync(0xffffffffu, mx0, 2));
            mx1 = fmaxf(mx1, __shfl_xor_sync(0xffffffffu, mx1, 1));
            mx1 = fmaxf(mx1, __shfl_xor_sync(0xffffffffu, mx1, 2));
            float mn0 = fmaxf(m0, mx0), mn1 = fmaxf(m1, mx1);
            float sc0 = __expf(m0 - mn0), sc1 = __expf(m1 - mn1);
            float sum0 = 0.f, sum1 = 0.f;
            #pragma unroll
            for (int nt = 0; nt < 8; nt++) {
                sacc[nt][0] = __expf(sacc[nt][0] - mn0);
                sacc[nt][1] = __expf(sacc[nt][1] - mn0);
                sacc[nt][2] = __expf(sacc[nt][2] - mn1);
                sacc[nt][3] = __expf(sacc[nt][3] - mn1);
                sum0 += sacc[nt][0] + sacc[nt][1];
                sum1 += sacc[nt][2] + sacc[nt][3];
            }
            sum0 += __shfl_xor_sync(0xffffffffu, sum0, 1);
            sum0 += __shfl_xor_sync(0xffffffffu, sum0, 2);
            sum1 += __shfl_xor_sync(0xffffffffu, sum1, 1);
            sum1 += __shfl_xor_sync(0xffffffffu, sum1, 2);
            l0 = l0 * sc0 + sum0;  l1 = l1 * sc1 + sum1;
            m0 = mn0;  m1 = mn1;
            #pragma unroll
            for (int nt = 0; nt < 8; nt++) {
                o[nt][0] *= sc0;  o[nt][1] *= sc0;
                o[nt][2] *= sc1;  o[nt][3] *= sc1;
            }

            // ---- O += PhVh + PhVl + PlVh (full hi/lo PV) ----
            #pragma unroll
            for (int kt = 0; kt < 4; kt++) {
                const float* sA = sacc[2*kt];
                const float* sB = sacc[2*kt+1];
                u32 pH[4], pL[4];
                pH[0] = bf2(sA[0], sA[1]);
                pH[1] = bf2(sA[2], sA[3]);
                pH[2] = bf2(sB[0], sB[1]);
                pH[3] = bf2(sB[2], sB[3]);
                pL[0] = bf2(sA[0] - lo16f(pH[0]), sA[1] - hi16f(pH[0]));
                pL[1] = bf2(sA[2] - lo16f(pH[1]), sA[3] - hi16f(pH[1]));
                pL[2] = bf2(sB[0] - lo16f(pH[2]), sB[1] - hi16f(pH[2]));
                pL[3] = bf2(sB[2] - lo16f(pH[3]), sB[3] - hi16f(pH[3]));
                #pragma unroll
                for (int ntp = 0; ntp < 4; ntp++) {
                    int nr = ntp * 16 + browB;
                    u32 off = (u32)(nr * 128 + (((kt * 2 + bgB) ^ (nr & 7)) << 4));
                    u32 vh4[4], vl4[4];
                    ldsm4(vh4, vbh + off);
                    ldsm4(vl4, vbl + off);
                    mma_bf16(o[2*ntp],   pH, vh4);
                    mma_bf16(o[2*ntp],   pH, vl4);
                    mma_bf16(o[2*ntp],   pL, vh4);
                    mma_bf16(o[2*ntp+1], pH, vh4 + 2);
                    mma_bf16(o[2*ntp+1], pH, vl4 + 2);
                    mma_bf16(o[2*ntp+1], pL, vh4 + 2);
                }
            }

            __syncthreads();
            if (tid == 0 && gi + 2 < n_iter) {
                const size_t tn = (size_t)(b * 64 + gi + 2) * 8192;
                u32 mb = s ? mb1 : mb0;
                u32 d  = smb + A_ST + s * A_STG;
                mbar_expect(mb, A_STG);
                bulk_g2s(d,         kh_g  + tn, 8192, mb);
                bulk_g2s(d + 8192,  vth_g + tn, 8192, mb);
                bulk_g2s(d + 16384, vtl_g + tn, 8192, mb);
            }
        }

        // ---- epilogue ----
        float i0 = 1.0f / l0, i1 = 1.0f / l1;
        int gr = b * TT + tq * 64 + warp * 16 + (lane >> 2);
        #pragma unroll
        for (int nt = 0; nt < 8; nt++) {
            int h = nt * 8 + 2 * (lane & 3);
            float2 w0 = make_float2(o[nt][0] * i0, o[nt][1] * i0);
            float2 w1 = make_float2(o[nt][2] * i1, o[nt][3] * i1);
            *(float2*)&out[(size_t)gr * HD + h]       = w0;
            *(float2*)&out[(size_t)(gr + 8) * HD + h] = w1;
        }
    }
}

extern "C" void kernel_launch(void* const* d_in, const int* in_sizes, int n_in,
                              void* d_out, int out_size)
{
    const float* x  = (const float*)d_in[0];
    const float* Wk = (const float*)d_in[1];
    const float* Wq = (const float*)d_in[2];
    const float* Wv = (const float*)d_in[3];
    float* out = (float*)d_out;

    cudaFuncSetAttribute(proj_kernel, cudaFuncAttributeMaxDynamicSharedMemorySize, P_SMEM);
    cudaFuncSetAttribute(attn2_kernel, cudaFuncAttributeMaxDynamicSharedMemorySize, A_SMEM);

    wconv_kernel<<<192, 256>>>(Wk, Wq, Wv);
    proj_kernel<<<BT / 128, 256, P_SMEM>>>(x);
    attn2_kernel<<<dim3(32, NB), 128, A_SMEM>>>(out);
}